// round 2
// baseline (speedup 1.0000x reference)
#include <cuda_runtime.h>
#include <cuda_bf16.h>
#include <cstddef>
#include <cstdint>

// Problem constants
#define BB   4
#define PP   1024
#define DD   1024
#define HH   16
#define DQK  64
#define DV   64
#define DMID 4096
#define EPS  1e-5f

// ---------------------------------------------------------------------------
// Scratch: one big __device__ global (no allocations allowed).
// Layout (floats):
//   q      : 4,194,304   (reused for y after scores GEMM)
//   k      : 4,194,304
//   v      : 4,194,304
//   scores : 67,108,864
//   o      : 4,194,304
//   xsa    : 4,194,304
//   x1     : 4,194,304
//   h      : 16,777,216
//   t      : 8,388,608
// total = 117,440,512 floats (~470 MB)
// y aliases q's slot (q is dead after the scores GEMM).
// ---------------------------------------------------------------------------
__device__ float g_scratch[117440512];

#define OFF_Q      0
#define OFF_K      4194304
#define OFF_V      8388608
#define OFF_SC     12582912
#define OFF_O      79691776
#define OFF_XSA    83886080
#define OFF_X1     88080384
#define OFF_H      92274688
#define OFF_T      109051904
#define OFF_Y      OFF_Q            // alias: q dead after scores GEMM

// ---------------------------------------------------------------------------
// Generic tiled SGEMM: C = alpha * A @ op(B) + bias
//   A: M x K, row-major, leading dim lda
//   TRANSB=true : B is N x K row-major  (C = A @ B^T)
//   TRANSB=false: B is K x N row-major  (C = A @ B)
// Batched via blockIdx.z: per-operand offset = (z/div)*outer + (z%div)*inner
// Tile 64x64x16, 256 threads, 4x4 per thread.
// ---------------------------------------------------------------------------
template <bool TRANSB>
__global__ __launch_bounds__(256)
void sgemm_kernel(const float* __restrict__ A, const float* __restrict__ B,
                  const float* __restrict__ bias, float* __restrict__ C,
                  int M, int N, int K, int lda, int ldb, int ldc,
                  int div,
                  long long aOuter, long long aInner,
                  long long bOuter, long long bInner,
                  long long cOuter, long long cInner,
                  float alpha)
{
    const int z = blockIdx.z;
    A += (long long)(z / div) * aOuter + (long long)(z % div) * aInner;
    B += (long long)(z / div) * bOuter + (long long)(z % div) * bInner;
    C += (long long)(z / div) * cOuter + (long long)(z % div) * cInner;

    __shared__ float As[16][68];
    __shared__ float Bs[16][68];

    const int tid = threadIdx.x;
    const int tx = tid & 15;      // 0..15 -> N direction (x4)
    const int ty = tid >> 4;      // 0..15 -> M direction (x4)
    const int m0 = blockIdx.y * 64;
    const int n0 = blockIdx.x * 64;

    float acc[4][4] = {};

    for (int k0 = 0; k0 < K; k0 += 16) {
        // Load A tile (64 rows x 16 k), transposed into As[kk][m]
        {
            const int kk = tid & 15;
            const int m  = tid >> 4;
#pragma unroll
            for (int p = 0; p < 4; p++)
                As[kk][m + p * 16] = A[(size_t)(m0 + m + p * 16) * lda + k0 + kk];
        }
        if (TRANSB) {
            const int kk = tid & 15;
            const int n  = tid >> 4;
#pragma unroll
            for (int p = 0; p < 4; p++)
                Bs[kk][n + p * 16] = B[(size_t)(n0 + n + p * 16) * ldb + k0 + kk];
        } else {
            const int n  = tid & 63;
            const int kk = tid >> 6;
#pragma unroll
            for (int p = 0; p < 4; p++)
                Bs[kk + p * 4][n] = B[(size_t)(k0 + kk + p * 4) * ldb + n0 + n];
        }
        __syncthreads();

#pragma unroll
        for (int kk = 0; kk < 16; kk++) {
            const float4 ra = *(const float4*)&As[kk][ty * 4];
            const float4 rb = *(const float4*)&Bs[kk][tx * 4];
            const float a0 = ra.x, a1 = ra.y, a2 = ra.z, a3 = ra.w;
            const float b0 = rb.x, b1 = rb.y, b2 = rb.z, b3 = rb.w;
            acc[0][0] = fmaf(a0, b0, acc[0][0]);
            acc[0][1] = fmaf(a0, b1, acc[0][1]);
            acc[0][2] = fmaf(a0, b2, acc[0][2]);
            acc[0][3] = fmaf(a0, b3, acc[0][3]);
            acc[1][0] = fmaf(a1, b0, acc[1][0]);
            acc[1][1] = fmaf(a1, b1, acc[1][1]);
            acc[1][2] = fmaf(a1, b2, acc[1][2]);
            acc[1][3] = fmaf(a1, b3, acc[1][3]);
            acc[2][0] = fmaf(a2, b0, acc[2][0]);
            acc[2][1] = fmaf(a2, b1, acc[2][1]);
            acc[2][2] = fmaf(a2, b2, acc[2][2]);
            acc[2][3] = fmaf(a2, b3, acc[2][3]);
            acc[3][0] = fmaf(a3, b0, acc[3][0]);
            acc[3][1] = fmaf(a3, b1, acc[3][1]);
            acc[3][2] = fmaf(a3, b2, acc[3][2]);
            acc[3][3] = fmaf(a3, b3, acc[3][3]);
        }
        __syncthreads();
    }

    // Epilogue: scale + optional bias + vectorized store
#pragma unroll
    for (int i = 0; i < 4; i++) {
        const int m = m0 + ty * 4 + i;
        const int n = n0 + tx * 4;
        float4 v;
        v.x = acc[i][0] * alpha;
        v.y = acc[i][1] * alpha;
        v.z = acc[i][2] * alpha;
        v.w = acc[i][3] * alpha;
        if (bias) {
            const float4 bv = *(const float4*)&bias[n];
            v.x += bv.x; v.y += bv.y; v.z += bv.z; v.w += bv.w;
        }
        *(float4*)&C[(size_t)m * ldc + n] = v;
    }
}

// ---------------------------------------------------------------------------
// Head-mix + attn_prev + softmax.
// One CTA per (b, q). Stages scores[b, :, q, :] (16 x 1024 fp32 = 64 KB) in
// dynamic smem, applies mixed[g,k] = sum_h W_th[g,h]*scores[h,k] + prev[g,k],
// then row-softmax over k, writing attn[b, g, q, :].
// ---------------------------------------------------------------------------
#define MIX_SMEM_BYTES ((16 * 1024 + 256 + 8) * 4)

__global__ __launch_bounds__(256)
void mix_softmax_kernel(const float* __restrict__ scores,
                        const float* __restrict__ attn_prev,
                        const float* __restrict__ W_th,
                        float* __restrict__ attn)
{
    extern __shared__ float sh[];
    float* s_sc  = sh;                 // 16*1024
    float* s_w   = sh + 16 * 1024;     // 256
    float* s_red = s_w + 256;          // 8

    const int tid = threadIdx.x;
    const int bq  = blockIdx.x;
    const int b   = bq >> 10;
    const int q   = bq & 1023;
    const int lane = tid & 31;
    const int warp = tid >> 5;

#pragma unroll
    for (int h = 0; h < 16; h++) {
        const float4* src =
            (const float4*)(scores + ((size_t)(b * 16 + h) * 1024 + q) * 1024);
        ((float4*)(s_sc + h * 1024))[tid] = src[tid];
    }
    if (tid < 256) s_w[tid] = W_th[tid];
    __syncthreads();

    for (int g = 0; g < 16; g++) {
        const size_t rowbase = ((size_t)(b * 16 + g) * 1024 + q) * 1024;
        const float* prev = attn_prev + rowbase;
        float* dst = attn + rowbase;

        float vals[4];
        float mx = -1e30f;
#pragma unroll
        for (int i = 0; i < 4; i++) {
            const int k = tid + i * 256;
            float acc = prev[k];
#pragma unroll
            for (int h = 0; h < 16; h++)
                acc = fmaf(s_w[g * 16 + h], s_sc[h * 1024 + k], acc);
            vals[i] = acc;
            mx = fmaxf(mx, acc);
        }
        // block max
#pragma unroll
        for (int o = 16; o; o >>= 1)
            mx = fmaxf(mx, __shfl_xor_sync(0xffffffffu, mx, o));
        if (lane == 0) s_red[warp] = mx;
        __syncthreads();
        float m = s_red[0];
#pragma unroll
        for (int w = 1; w < 8; w++) m = fmaxf(m, s_red[w]);
        __syncthreads();

        float sum = 0.f;
#pragma unroll
        for (int i = 0; i < 4; i++) {
            vals[i] = __expf(vals[i] - m);
            sum += vals[i];
        }
#pragma unroll
        for (int o = 16; o; o >>= 1)
            sum += __shfl_xor_sync(0xffffffffu, sum, o);
        if (lane == 0) s_red[warp] = sum;
        __syncthreads();
        float tot = 0.f;
#pragma unroll
        for (int w = 0; w < 8; w++) tot += s_red[w];
        const float inv = 1.0f / tot;
#pragma unroll
        for (int i = 0; i < 4; i++) dst[tid + i * 256] = vals[i] * inv;
        __syncthreads();
    }
}

// ---------------------------------------------------------------------------
// out = LayerNorm(a + b) * gamma + beta, rows of 1024. One CTA per row.
// ---------------------------------------------------------------------------
__global__ __launch_bounds__(256)
void add_ln_kernel(const float* __restrict__ a, const float* __restrict__ b,
                   const float* __restrict__ gam, const float* __restrict__ bet,
                   float* __restrict__ out)
{
    __shared__ float s_red[8];
    __shared__ float s_red2[8];
    const int row = blockIdx.x;
    const int tid = threadIdx.x;
    const int lane = tid & 31, warp = tid >> 5;

    const float4 va = ((const float4*)(a + (size_t)row * 1024))[tid];
    const float4 vb = ((const float4*)(b + (size_t)row * 1024))[tid];
    float4 v;
    v.x = va.x + vb.x; v.y = va.y + vb.y; v.z = va.z + vb.z; v.w = va.w + vb.w;

    float s  = v.x + v.y + v.z + v.w;
    float s2 = v.x * v.x + v.y * v.y + v.z * v.z + v.w * v.w;
#pragma unroll
    for (int o = 16; o; o >>= 1) {
        s  += __shfl_xor_sync(0xffffffffu, s, o);
        s2 += __shfl_xor_sync(0xffffffffu, s2, o);
    }
    if (lane == 0) { s_red[warp] = s; s_red2[warp] = s2; }
    __syncthreads();
    float ts = 0.f, ts2 = 0.f;
#pragma unroll
    for (int w = 0; w < 8; w++) { ts += s_red[w]; ts2 += s_red2[w]; }

    const float mu  = ts * (1.0f / 1024.0f);
    const float var = ts2 * (1.0f / 1024.0f) - mu * mu;
    const float inv = rsqrtf(var + EPS);

    const float4 g4 = ((const float4*)gam)[tid];
    const float4 b4 = ((const float4*)bet)[tid];
    float4 o;
    o.x = (v.x - mu) * inv * g4.x + b4.x;
    o.y = (v.y - mu) * inv * g4.y + b4.y;
    o.z = (v.z - mu) * inv * g4.z + b4.z;
    o.w = (v.w - mu) * inv * g4.w + b4.w;
    ((float4*)(out + (size_t)row * 1024))[tid] = o;
}

// ---------------------------------------------------------------------------
// GLU: t[r, j] = h[r, j] * relu(h[r, 2048 + j])
// ---------------------------------------------------------------------------
__global__ __launch_bounds__(256)
void glu_kernel(const float* __restrict__ h, float* __restrict__ t)
{
    const int i = blockIdx.x * blockDim.x + threadIdx.x;  // over 2,097,152 f4
    const int r = i >> 9;
    const int j = i & 511;
    const float4* hr = (const float4*)(h + (size_t)r * 4096);
    const float4 a = hr[j];
    const float4 g = hr[512 + j];
    float4 o;
    o.x = a.x * fmaxf(g.x, 0.f);
    o.y = a.y * fmaxf(g.y, 0.f);
    o.z = a.z * fmaxf(g.z, 0.f);
    o.w = a.w * fmaxf(g.w, 0.f);
    ((float4*)t)[i] = o;
}

// ---------------------------------------------------------------------------
// Launcher
// ---------------------------------------------------------------------------
extern "C" void kernel_launch(void* const* d_in, const int* in_sizes, int n_in,
                              void* d_out, int out_size)
{
    const float* x         = (const float*)d_in[0];
    const float* attn_prev = (const float*)d_in[1];
    const float* Wq        = (const float*)d_in[2];
    const float* Wk        = (const float*)d_in[3];
    const float* Wv        = (const float*)d_in[4];
    const float* W_th      = (const float*)d_in[5];
    const float* Wpv       = (const float*)d_in[6];
    const float* W1        = (const float*)d_in[7];
    const float* b1        = (const float*)d_in[8];
    const float* W2        = (const float*)d_in[9];
    const float* b2        = (const float*)d_in[10];
    const float* ln1g      = (const float*)d_in[11];
    const float* ln1b      = (const float*)d_in[12];
    const float* ln2g      = (const float*)d_in[13];
    const float* ln2b      = (const float*)d_in[14];

    float* out  = (float*)d_out;                        // (B, P, D)
    float* attn = out + (size_t)BB * PP * DD;           // (B, H, P, P)

    float* s = nullptr;
    cudaGetSymbolAddress((void**)&s, g_scratch);
    float* qb  = s + OFF_Q;
    float* kb  = s + OFF_K;
    float* vb  = s + OFF_V;
    float* sc  = s + OFF_SC;
    float* ob  = s + OFF_O;
    float* xsa = s + OFF_XSA;
    float* x1  = s + OFF_X1;
    float* hb  = s + OFF_H;
    float* tb  = s + OFF_T;
    float* yb  = s + OFF_Y;    // aliases qb (q dead after scores GEMM)

    cudaFuncSetAttribute(mix_softmax_kernel,
                         cudaFuncAttributeMaxDynamicSharedMemorySize,
                         MIX_SMEM_BYTES);

    const int M  = BB * PP;          // 4096
    const long long zero = 0;

    // 1-3: Q, K, V projections  (M=4096, N=1024, K=1024), NT
    {
        dim3 grid(DD / 64, M / 64, 1);
        sgemm_kernel<true><<<grid, 256>>>(x, Wq, nullptr, qb,
            M, HH * DQK, DD, DD, DD, HH * DQK,
            1, zero, zero, zero, zero, zero, zero, 0.125f);
        sgemm_kernel<true><<<grid, 256>>>(x, Wk, nullptr, kb,
            M, HH * DQK, DD, DD, DD, HH * DQK,
            1, zero, zero, zero, zero, zero, zero, 1.0f);
        sgemm_kernel<true><<<grid, 256>>>(x, Wv, nullptr, vb,
            M, HH * DV, DD, DD, DD, HH * DV,
            1, zero, zero, zero, zero, zero, zero, 1.0f);
    }

    // 4: scores[b,h] = q_bh @ k_bh^T   (batched over 64 = B*H)
    {
        dim3 grid(PP / 64, PP / 64, BB * HH);
        sgemm_kernel<true><<<grid, 256>>>(qb, kb, nullptr, sc,
            PP, PP, DQK, HH * DQK, HH * DQK, PP,
            HH,
            (long long)PP * 1024, (long long)DQK,     // A: b-stride, h-stride
            (long long)PP * 1024, (long long)DQK,     // B
            (long long)HH * PP * PP, (long long)PP * PP,  // C
            1.0f);
    }

    // 5: head mix + attn_prev + softmax -> attn (into d_out)
    mix_softmax_kernel<<<BB * PP, 256, MIX_SMEM_BYTES>>>(sc, attn_prev, W_th, attn);

    // 6: o[b,h] = attn_bh @ v_bh   (NN, batched over 64)
    {
        dim3 grid(DV / 64, PP / 64, BB * HH);
        sgemm_kernel<false><<<grid, 256>>>(attn, vb, nullptr, ob,
            PP, DV, PP, PP, HH * DV, HH * DV,
            HH,
            (long long)HH * PP * PP, (long long)PP * PP,  // A
            (long long)PP * 1024, (long long)DV,          // B
            (long long)PP * 1024, (long long)DV,          // C
            1.0f);
    }

    // 7: x_sa = o @ Wpv^T
    {
        dim3 grid(DD / 64, M / 64, 1);
        sgemm_kernel<true><<<grid, 256>>>(ob, Wpv, nullptr, xsa,
            M, DD, HH * DV, HH * DV, HH * DV, DD,
            1, zero, zero, zero, zero, zero, zero, 1.0f);
    }

    // 8: x1 = LN(x + x_sa)
    add_ln_kernel<<<M, 256>>>(x, xsa, ln1g, ln1b, x1);

    // 9: h = x1 @ W1^T + b1   (N=4096)
    {
        dim3 grid(DMID / 64, M / 64, 1);
        sgemm_kernel<true><<<grid, 256>>>(x1, W1, b1, hb,
            M, DMID, DD, DD, DD, DMID,
            1, zero, zero, zero, zero, zero, zero, 1.0f);
    }

    // 10: GLU -> t  (M x 2048)
    glu_kernel<<<(M * (DMID / 2) / 4) / 256, 256>>>(hb, tb);

    // 11: y = t @ W2^T + b2   (K=2048)
    {
        dim3 grid(DD / 64, M / 64, 1);
        sgemm_kernel<true><<<grid, 256>>>(tb, W2, b2, yb,
            M, DD, DMID / 2, DMID / 2, DMID / 2, DD,
            1, zero, zero, zero, zero, zero, zero, 1.0f);
    }

    // 12: out = LN(x1 + y)
    add_ln_kernel<<<M, 256>>>(x1, yb, ln2g, ln2b, out);
}

// round 3
// speedup vs baseline: 2.8519x; 2.8519x over previous
#include <cuda_runtime.h>
#include <cuda_bf16.h>
#include <cstddef>
#include <cstdint>

// Problem constants
#define BB   4
#define PP   1024
#define DD   1024
#define HH   16
#define DQK  64
#define DV   64
#define DMID 4096
#define EPS  1e-5f

// ---------------------------------------------------------------------------
// Scratch (no allocations allowed). y aliases q (q dead after scores GEMM).
// ---------------------------------------------------------------------------
__device__ float g_scratch[117440512];

#define OFF_Q      0
#define OFF_K      4194304
#define OFF_V      8388608
#define OFF_SC     12582912
#define OFF_O      79691776
#define OFF_XSA    83886080
#define OFF_X1     88080384
#define OFF_H      92274688
#define OFF_T      109051904
#define OFF_Y      OFF_Q

// ---------------------------------------------------------------------------
// PTX helpers
// ---------------------------------------------------------------------------
__device__ __forceinline__ uint32_t smem_u32(const void* p) {
    return (uint32_t)__cvta_generic_to_shared(p);
}
__device__ __forceinline__ void cp_async16(uint32_t dst, const float* src) {
    asm volatile("cp.async.cg.shared.global [%0], [%1], 16;\n" :: "r"(dst), "l"(src));
}
__device__ __forceinline__ void cp_commit() {
    asm volatile("cp.async.commit_group;\n");
}
template <int N>
__device__ __forceinline__ void cp_wait() {
    asm volatile("cp.async.wait_group %0;\n" :: "n"(N));
}
__device__ __forceinline__ uint32_t f2tf32(float f) {
    uint32_t r;
    asm("cvt.rna.tf32.f32 %0, %1;\n" : "=r"(r) : "f"(f));
    return r;
}
__device__ __forceinline__ void mma_tf32(float& c0, float& c1, float& c2, float& c3,
                                         uint32_t a0, uint32_t a1, uint32_t a2, uint32_t a3,
                                         uint32_t b0, uint32_t b1) {
    asm volatile(
        "mma.sync.aligned.m16n8k8.row.col.f32.tf32.tf32.f32 "
        "{%0,%1,%2,%3},{%4,%5,%6,%7},{%8,%9},{%0,%1,%2,%3};\n"
        : "+f"(c0), "+f"(c1), "+f"(c2), "+f"(c3)
        : "r"(a0), "r"(a1), "r"(a2), "r"(a3), "r"(b0), "r"(b1));
}

// ---------------------------------------------------------------------------
// TF32 tensor-core GEMM: C = alpha * A @ op(B) + bias
//   A: M x K row-major (lda).
//   TRANSB=true : B is N x K row-major (C = A @ B^T)
//   TRANSB=false: B is K x N row-major (C = A @ B)
// Tile: BM=128 x BN x BK=32, 3-stage cp.async pipeline, 256 threads (8 warps,
// 4x2 warp grid). Swizzled smem for A / B^T; padded [k][n] for B (NN).
// Batched via blockIdx.z: offset = (z/div)*outer + (z%div)*inner.
// Requires: M % 128 == 0, N % BN == 0, K % 32 == 0, all ptrs 16B-aligned,
// lda/ldb/ldc % 4 == 0.
// ---------------------------------------------------------------------------
template <int BN, bool TRANSB>
__global__ __launch_bounds__(256, 2)
void tgemm_kernel(const float* __restrict__ A, const float* __restrict__ B,
                  const float* __restrict__ bias, float* __restrict__ C,
                  int M, int N, int K, int lda, int ldb, int ldc,
                  int div,
                  long long aOuter, long long aInner,
                  long long bOuter, long long bInner,
                  long long cOuter, long long cInner,
                  float alpha)
{
    constexpr int BM = 128;
    constexpr int BK = 32;
    constexpr int STAGES = 3;
    constexpr int NT = (BN / 2) / 8;            // mma n-tiles per warp
    constexpr int ASZ = BM * BK;                // swizzled [m][k], no pad
    constexpr int LDB_S = BN + 8;               // NN layout pad
    constexpr int BSZ = TRANSB ? (BN * BK) : (BK * LDB_S);

    const int z = blockIdx.z;
    A += (long long)(z / div) * aOuter + (long long)(z % div) * aInner;
    B += (long long)(z / div) * bOuter + (long long)(z % div) * bInner;
    C += (long long)(z / div) * cOuter + (long long)(z % div) * cInner;

    extern __shared__ float sm[];
    float* Asm = sm;                   // [STAGES][ASZ]
    float* Bsm = sm + STAGES * ASZ;    // [STAGES][BSZ]

    const int tid  = threadIdx.x;
    const int lane = tid & 31;
    const int warp = tid >> 5;
    const int warp_m = (warp >> 1) * 32;
    const int warp_n = (warp & 1) * (BN / 2);
    const int m0 = blockIdx.y * BM;
    const int n0 = blockIdx.x * BN;
    const int Kiters = K / BK;

    const uint32_t a_base = smem_u32(Asm);
    const uint32_t b_base = smem_u32(Bsm);

    // ---- stage loader ----
    auto issue_stage = [&](int it) {
        if (it < Kiters) {
            const int s  = it % STAGES;
            const int k0 = it * BK;
            // A: 128x32 floats = 1024 f4, 4 per thread. swizzle: f4idx = r*8 + (g^(r&7))
#pragma unroll
            for (int i = 0; i < 4; i++) {
                const int idx = tid + i * 256;
                const int r = idx >> 3;
                const int g = idx & 7;
                const float* src = A + (size_t)(m0 + r) * lda + k0 + g * 4;
                cp_async16(a_base + (uint32_t)(s * ASZ + (r * 8 + (g ^ (r & 7))) * 4) * 4, src);
            }
            if (TRANSB) {
                // B^T: BN x 32 floats, same swizzled layout keyed by n-row
#pragma unroll
                for (int i = 0; i < BN / 32; i++) {
                    const int idx = tid + i * 256;
                    const int r = idx >> 3;
                    const int g = idx & 7;
                    const float* src = B + (size_t)(n0 + r) * ldb + k0 + g * 4;
                    cp_async16(b_base + (uint32_t)(s * BSZ + (r * 8 + (g ^ (r & 7))) * 4) * 4, src);
                }
            } else {
                // B (NN): 32 rows x BN floats into [k][n] with LDB_S pad
#pragma unroll
                for (int i = 0; i < BN / 32; i++) {
                    const int idx = tid + i * 256;          // over 32*(BN/4) f4
                    const int r = idx / (BN / 4);
                    const int g = idx % (BN / 4);
                    const float* src = B + (size_t)(k0 + r) * ldb + n0 + g * 4;
                    cp_async16(b_base + (uint32_t)(s * BSZ + r * LDB_S + g * 4) * 4, src);
                }
            }
        }
        cp_commit();
    };

    float acc[2][NT][4];
#pragma unroll
    for (int mi = 0; mi < 2; mi++)
#pragma unroll
        for (int nj = 0; nj < NT; nj++)
#pragma unroll
            for (int c = 0; c < 4; c++) acc[mi][nj][c] = 0.f;

    issue_stage(0);
    issue_stage(1);

    const int e = lane & 3;
    const int qd = lane >> 2;

    for (int it = 0; it < Kiters; ++it) {
        cp_wait<1>();
        __syncthreads();
        issue_stage(it + 2);

        const float* as = Asm + (it % STAGES) * ASZ;
        const float* bs = Bsm + (it % STAGES) * BSZ;

#pragma unroll
        for (int ks = 0; ks < 4; ks++) {
            const int g0 = ks * 2, g1 = ks * 2 + 1;
            uint32_t af[2][4];
#pragma unroll
            for (int mi = 0; mi < 2; mi++) {
                const int r0 = warp_m + mi * 16 + qd;
                const int r1 = r0 + 8;
                af[mi][0] = f2tf32(as[r0 * 32 + ((g0 ^ (r0 & 7)) << 2) + e]);
                af[mi][1] = f2tf32(as[r1 * 32 + ((g0 ^ (r1 & 7)) << 2) + e]);
                af[mi][2] = f2tf32(as[r0 * 32 + ((g1 ^ (r0 & 7)) << 2) + e]);
                af[mi][3] = f2tf32(as[r1 * 32 + ((g1 ^ (r1 & 7)) << 2) + e]);
            }
            uint32_t bf[NT][2];
#pragma unroll
            for (int nj = 0; nj < NT; nj++) {
                if (TRANSB) {
                    const int r = warp_n + nj * 8 + qd;
                    bf[nj][0] = f2tf32(bs[r * 32 + ((g0 ^ (r & 7)) << 2) + e]);
                    bf[nj][1] = f2tf32(bs[r * 32 + ((g1 ^ (r & 7)) << 2) + e]);
                } else {
                    const int n = warp_n + nj * 8 + qd;
                    bf[nj][0] = f2tf32(bs[(ks * 8 + e) * LDB_S + n]);
                    bf[nj][1] = f2tf32(bs[(ks * 8 + e + 4) * LDB_S + n]);
                }
            }
#pragma unroll
            for (int mi = 0; mi < 2; mi++)
#pragma unroll
                for (int nj = 0; nj < NT; nj++)
                    mma_tf32(acc[mi][nj][0], acc[mi][nj][1], acc[mi][nj][2], acc[mi][nj][3],
                             af[mi][0], af[mi][1], af[mi][2], af[mi][3],
                             bf[nj][0], bf[nj][1]);
        }
        __syncthreads();
    }

    // ---- epilogue ----
#pragma unroll
    for (int mi = 0; mi < 2; mi++) {
#pragma unroll
        for (int nj = 0; nj < NT; nj++) {
            const int row0 = m0 + warp_m + mi * 16 + qd;
            const int col  = n0 + warp_n + nj * 8 + e * 2;
            float2 v0, v1;
            v0.x = acc[mi][nj][0] * alpha;
            v0.y = acc[mi][nj][1] * alpha;
            v1.x = acc[mi][nj][2] * alpha;
            v1.y = acc[mi][nj][3] * alpha;
            if (bias) {
                const float b0 = bias[col], b1 = bias[col + 1];
                v0.x += b0; v0.y += b1;
                v1.x += b0; v1.y += b1;
            }
            *(float2*)&C[(size_t)row0 * ldc + col] = v0;
            *(float2*)&C[(size_t)(row0 + 8) * ldc + col] = v1;
        }
    }
}

// ---------------------------------------------------------------------------
// Head-mix + attn_prev + softmax. One CTA per (b, q).
// ---------------------------------------------------------------------------
#define MIX_SMEM_BYTES ((16 * 1024 + 256 + 8) * 4)

__global__ __launch_bounds__(256)
void mix_softmax_kernel(const float* __restrict__ scores,
                        const float* __restrict__ attn_prev,
                        const float* __restrict__ W_th,
                        float* __restrict__ attn)
{
    extern __shared__ float sh[];
    float* s_sc  = sh;
    float* s_w   = sh + 16 * 1024;
    float* s_red = s_w + 256;

    const int tid = threadIdx.x;
    const int bq  = blockIdx.x;
    const int b   = bq >> 10;
    const int q   = bq & 1023;
    const int lane = tid & 31;
    const int warp = tid >> 5;

#pragma unroll
    for (int h = 0; h < 16; h++) {
        const float4* src =
            (const float4*)(scores + ((size_t)(b * 16 + h) * 1024 + q) * 1024);
        ((float4*)(s_sc + h * 1024))[tid] = src[tid];
    }
    if (tid < 256) s_w[tid] = W_th[tid];
    __syncthreads();

    for (int g = 0; g < 16; g++) {
        const size_t rowbase = ((size_t)(b * 16 + g) * 1024 + q) * 1024;
        const float* prev = attn_prev + rowbase;
        float* dst = attn + rowbase;

        float vals[4];
        float mx = -1e30f;
#pragma unroll
        for (int i = 0; i < 4; i++) {
            const int k = tid + i * 256;
            float acc = prev[k];
#pragma unroll
            for (int h = 0; h < 16; h++)
                acc = fmaf(s_w[g * 16 + h], s_sc[h * 1024 + k], acc);
            vals[i] = acc;
            mx = fmaxf(mx, acc);
        }
#pragma unroll
        for (int o = 16; o; o >>= 1)
            mx = fmaxf(mx, __shfl_xor_sync(0xffffffffu, mx, o));
        if (lane == 0) s_red[warp] = mx;
        __syncthreads();
        float m = s_red[0];
#pragma unroll
        for (int w = 1; w < 8; w++) m = fmaxf(m, s_red[w]);
        __syncthreads();

        float sum = 0.f;
#pragma unroll
        for (int i = 0; i < 4; i++) {
            vals[i] = __expf(vals[i] - m);
            sum += vals[i];
        }
#pragma unroll
        for (int o = 16; o; o >>= 1)
            sum += __shfl_xor_sync(0xffffffffu, sum, o);
        if (lane == 0) s_red[warp] = sum;
        __syncthreads();
        float tot = 0.f;
#pragma unroll
        for (int w = 0; w < 8; w++) tot += s_red[w];
        const float inv = 1.0f / tot;
#pragma unroll
        for (int i = 0; i < 4; i++) dst[tid + i * 256] = vals[i] * inv;
        __syncthreads();
    }
}

// ---------------------------------------------------------------------------
// out = LayerNorm(a + b) * gamma + beta, rows of 1024.
// ---------------------------------------------------------------------------
__global__ __launch_bounds__(256)
void add_ln_kernel(const float* __restrict__ a, const float* __restrict__ b,
                   const float* __restrict__ gam, const float* __restrict__ bet,
                   float* __restrict__ out)
{
    __shared__ float s_red[8];
    __shared__ float s_red2[8];
    const int row = blockIdx.x;
    const int tid = threadIdx.x;
    const int lane = tid & 31, warp = tid >> 5;

    const float4 va = ((const float4*)(a + (size_t)row * 1024))[tid];
    const float4 vb = ((const float4*)(b + (size_t)row * 1024))[tid];
    float4 v;
    v.x = va.x + vb.x; v.y = va.y + vb.y; v.z = va.z + vb.z; v.w = va.w + vb.w;

    float s  = v.x + v.y + v.z + v.w;
    float s2 = v.x * v.x + v.y * v.y + v.z * v.z + v.w * v.w;
#pragma unroll
    for (int o = 16; o; o >>= 1) {
        s  += __shfl_xor_sync(0xffffffffu, s, o);
        s2 += __shfl_xor_sync(0xffffffffu, s2, o);
    }
    if (lane == 0) { s_red[warp] = s; s_red2[warp] = s2; }
    __syncthreads();
    float ts = 0.f, ts2 = 0.f;
#pragma unroll
    for (int w = 0; w < 8; w++) { ts += s_red[w]; ts2 += s_red2[w]; }

    const float mu  = ts * (1.0f / 1024.0f);
    const float var = ts2 * (1.0f / 1024.0f) - mu * mu;
    const float inv = rsqrtf(var + EPS);

    const float4 g4 = ((const float4*)gam)[tid];
    const float4 b4 = ((const float4*)bet)[tid];
    float4 o;
    o.x = (v.x - mu) * inv * g4.x + b4.x;
    o.y = (v.y - mu) * inv * g4.y + b4.y;
    o.z = (v.z - mu) * inv * g4.z + b4.z;
    o.w = (v.w - mu) * inv * g4.w + b4.w;
    ((float4*)(out + (size_t)row * 1024))[tid] = o;
}

// ---------------------------------------------------------------------------
// GLU: t[r, j] = h[r, j] * relu(h[r, 2048 + j])
// ---------------------------------------------------------------------------
__global__ __launch_bounds__(256)
void glu_kernel(const float* __restrict__ h, float* __restrict__ t)
{
    const int i = blockIdx.x * blockDim.x + threadIdx.x;
    const int r = i >> 9;
    const int j = i & 511;
    const float4* hr = (const float4*)(h + (size_t)r * 4096);
    const float4 a = hr[j];
    const float4 g = hr[512 + j];
    float4 o;
    o.x = a.x * fmaxf(g.x, 0.f);
    o.y = a.y * fmaxf(g.y, 0.f);
    o.z = a.z * fmaxf(g.z, 0.f);
    o.w = a.w * fmaxf(g.w, 0.f);
    ((float4*)t)[i] = o;
}

// ---------------------------------------------------------------------------
// Launcher
// ---------------------------------------------------------------------------
extern "C" void kernel_launch(void* const* d_in, const int* in_sizes, int n_in,
                              void* d_out, int out_size)
{
    const float* x         = (const float*)d_in[0];
    const float* attn_prev = (const float*)d_in[1];
    const float* Wq        = (const float*)d_in[2];
    const float* Wk        = (const float*)d_in[3];
    const float* Wv        = (const float*)d_in[4];
    const float* W_th      = (const float*)d_in[5];
    const float* Wpv       = (const float*)d_in[6];
    const float* W1        = (const float*)d_in[7];
    const float* b1        = (const float*)d_in[8];
    const float* W2        = (const float*)d_in[9];
    const float* b2        = (const float*)d_in[10];
    const float* ln1g      = (const float*)d_in[11];
    const float* ln1b      = (const float*)d_in[12];
    const float* ln2g      = (const float*)d_in[13];
    const float* ln2b      = (const float*)d_in[14];

    float* out  = (float*)d_out;
    float* attn = out + (size_t)BB * PP * DD;

    float* s = nullptr;
    cudaGetSymbolAddress((void**)&s, g_scratch);
    float* qb  = s + OFF_Q;
    float* kb  = s + OFF_K;
    float* vb  = s + OFF_V;
    float* sc  = s + OFF_SC;
    float* ob  = s + OFF_O;
    float* xsa = s + OFF_XSA;
    float* x1  = s + OFF_X1;
    float* hb  = s + OFF_H;
    float* tb  = s + OFF_T;
    float* yb  = s + OFF_Y;

    // smem sizes: NT(128): 3*(4096+4096)*4 = 98304 B; NN(64): 3*(4096+32*72)*4 = 76800 B
    const int SM_NT  = 3 * (128 * 32 + 128 * 32) * 4;
    const int SM_NN  = 3 * (128 * 32 + 32 * (64 + 8)) * 4;
    cudaFuncSetAttribute((const void*)tgemm_kernel<128, true>,
                         cudaFuncAttributeMaxDynamicSharedMemorySize, SM_NT);
    cudaFuncSetAttribute((const void*)tgemm_kernel<64, false>,
                         cudaFuncAttributeMaxDynamicSharedMemorySize, SM_NN);
    cudaFuncSetAttribute(mix_softmax_kernel,
                         cudaFuncAttributeMaxDynamicSharedMemorySize, MIX_SMEM_BYTES);

    const int M = BB * PP;          // 4096
    const long long zero = 0;

    // 1-3: Q, K, V projections  (M=4096, N=1024, K=1024), NT
    {
        dim3 grid(DD / 128, M / 128, 1);
        tgemm_kernel<128, true><<<grid, 256, SM_NT>>>(x, Wq, nullptr, qb,
            M, HH * DQK, DD, DD, DD, HH * DQK,
            1, zero, zero, zero, zero, zero, zero, 0.125f);
        tgemm_kernel<128, true><<<grid, 256, SM_NT>>>(x, Wk, nullptr, kb,
            M, HH * DQK, DD, DD, DD, HH * DQK,
            1, zero, zero, zero, zero, zero, zero, 1.0f);
        tgemm_kernel<128, true><<<grid, 256, SM_NT>>>(x, Wv, nullptr, vb,
            M, HH * DV, DD, DD, DD, HH * DV,
            1, zero, zero, zero, zero, zero, zero, 1.0f);
    }

    // 4: scores[b,h] = q_bh @ k_bh^T   (batched over 64 = B*H), K=64
    {
        dim3 grid(PP / 128, PP / 128, BB * HH);
        tgemm_kernel<128, true><<<grid, 256, SM_NT>>>(qb, kb, nullptr, sc,
            PP, PP, DQK, HH * DQK, HH * DQK, PP,
            HH,
            (long long)PP * 1024, (long long)DQK,
            (long long)PP * 1024, (long long)DQK,
            (long long)HH * PP * PP, (long long)PP * PP,
            1.0f);
    }

    // 5: head mix + attn_prev + softmax -> attn (into d_out)
    mix_softmax_kernel<<<BB * PP, 256, MIX_SMEM_BYTES>>>(sc, attn_prev, W_th, attn);

    // 6: o[b,h] = attn_bh @ v_bh   (NN, batched over 64, N=64)
    {
        dim3 grid(1, PP / 128, BB * HH);
        tgemm_kernel<64, false><<<grid, 256, SM_NN>>>(attn, vb, nullptr, ob,
            PP, DV, PP, PP, HH * DV, HH * DV,
            HH,
            (long long)HH * PP * PP, (long long)PP * PP,
            (long long)PP * 1024, (long long)DV,
            (long long)PP * 1024, (long long)DV,
            1.0f);
    }

    // 7: x_sa = o @ Wpv^T
    {
        dim3 grid(DD / 128, M / 128, 1);
        tgemm_kernel<128, true><<<grid, 256, SM_NT>>>(ob, Wpv, nullptr, xsa,
            M, DD, HH * DV, HH * DV, HH * DV, DD,
            1, zero, zero, zero, zero, zero, zero, 1.0f);
    }

    // 8: x1 = LN(x + x_sa)
    add_ln_kernel<<<M, 256>>>(x, xsa, ln1g, ln1b, x1);

    // 9: h = x1 @ W1^T + b1   (N=4096)
    {
        dim3 grid(DMID / 128, M / 128, 1);
        tgemm_kernel<128, true><<<grid, 256, SM_NT>>>(x1, W1, b1, hb,
            M, DMID, DD, DD, DD, DMID,
            1, zero, zero, zero, zero, zero, zero, 1.0f);
    }

    // 10: GLU -> t  (M x 2048)
    glu_kernel<<<(M * (DMID / 2) / 4) / 256, 256>>>(hb, tb);

    // 11: y = t @ W2^T + b2   (K=2048)
    {
        dim3 grid(DD / 128, M / 128, 1);
        tgemm_kernel<128, true><<<grid, 256, SM_NT>>>(tb, W2, b2, yb,
            M, DD, DMID / 2, DMID / 2, DMID / 2, DD,
            1, zero, zero, zero, zero, zero, zero, 1.0f);
    }

    // 12: out = LN(x1 + y)
    add_ln_kernel<<<M, 256>>>(x1, yb, ln2g, ln2b, out);
}

// round 5
// speedup vs baseline: 3.1408x; 1.1013x over previous
#include <cuda_runtime.h>
#include <cuda_bf16.h>
#include <cstddef>
#include <cstdint>

// Problem constants
#define BB   4
#define PP   1024
#define DD   1024
#define HH   16
#define DQK  64
#define DV   64
#define DMID 4096
#define EPS  1e-5f

// ---------------------------------------------------------------------------
// Scratch layout (floats). Y aliases XR (xr dead after QKV projections).
// ---------------------------------------------------------------------------
__device__ float g_scratch[132120576];

#define OFF_XR     0            //  4,194,304
#define OFF_WQ     4194304      //  1,048,576
#define OFF_WK     5242880      //  1,048,576
#define OFF_WV     6291456      //  1,048,576
#define OFF_WPV    7340032      //  1,048,576
#define OFF_W1R    8388608      //  4,194,304
#define OFF_W2R    12582912     //  2,097,152
#define OFF_QB     14680064     //  4,194,304
#define OFF_KB     18874368     //  4,194,304
#define OFF_VB     23068672     //  4,194,304
#define OFF_SC     27262976     // 67,108,864
#define OFF_O      94371840     //  4,194,304
#define OFF_XSA    98566144     //  4,194,304
#define OFF_X1     102760448    //  4,194,304
#define OFF_H      106954752    // 16,777,216
#define OFF_T      123731968    //  8,388,608
#define OFF_Y      OFF_XR       //  alias

// ---------------------------------------------------------------------------
// PTX helpers
// ---------------------------------------------------------------------------
__device__ __forceinline__ uint32_t smem_u32(const void* p) {
    return (uint32_t)__cvta_generic_to_shared(p);
}
__device__ __forceinline__ void cp_async16(uint32_t dst, const float* src) {
    asm volatile("cp.async.cg.shared.global [%0], [%1], 16;\n" :: "r"(dst), "l"(src));
}
__device__ __forceinline__ void cp_commit() {
    asm volatile("cp.async.commit_group;\n");
}
template <int N>
__device__ __forceinline__ void cp_wait() {
    asm volatile("cp.async.wait_group %0;\n" :: "n"(N));
}
__device__ __forceinline__ uint32_t f2tf32(float f) {
    uint32_t r;
    asm("cvt.rna.tf32.f32 %0, %1;\n" : "=r"(r) : "f"(f));
    return r;
}
__device__ __forceinline__ float tf32r(float f) {
    return __uint_as_float(f2tf32(f));
}
__device__ __forceinline__ void mma_tf32(float& c0, float& c1, float& c2, float& c3,
                                         uint32_t a0, uint32_t a1, uint32_t a2, uint32_t a3,
                                         uint32_t b0, uint32_t b1) {
    asm volatile(
        "mma.sync.aligned.m16n8k8.row.col.f32.tf32.tf32.f32 "
        "{%0,%1,%2,%3},{%4,%5,%6,%7},{%8,%9},{%0,%1,%2,%3};\n"
        : "+f"(c0), "+f"(c1), "+f"(c2), "+f"(c3)
        : "r"(a0), "r"(a1), "r"(a2), "r"(a3), "r"(b0), "r"(b1));
}

// ---------------------------------------------------------------------------
// Prep: round-to-tf32 copy (bit-identical to cvt-at-load in the consumer)
// ---------------------------------------------------------------------------
__global__ __launch_bounds__(256)
void round_copy_kernel(const float* __restrict__ src, float* __restrict__ dst)
{
    const int i = blockIdx.x * 256 + threadIdx.x;
    const float4 v = ((const float4*)src)[i];
    float4 o;
    o.x = tf32r(v.x); o.y = tf32r(v.y); o.z = tf32r(v.z); o.w = tf32r(v.w);
    ((float4*)dst)[i] = o;
}

// ---------------------------------------------------------------------------
// TF32 tensor-core GEMM: C = alpha * A @ op(B) + bias
//   CVTA: apply cvt.rna.tf32 to A fragments at load (A not pre-rounded).
//   B operands must ALWAYS be pre-rounded to tf32.
//   EPI = 0: plain; EPI = 1: output rounded to tf32.
// ---------------------------------------------------------------------------
template <int BN, bool TRANSB, int EPI, bool CVTA>
__global__ __launch_bounds__(256, 2)
void tgemm_kernel(const float* __restrict__ A, const float* __restrict__ B,
                  const float* __restrict__ bias, float* __restrict__ C,
                  int M, int N, int K, int lda, int ldb, int ldc,
                  int div,
                  long long aOuter, long long aInner,
                  long long bOuter, long long bInner,
                  long long cOuter, long long cInner,
                  float alpha)
{
    constexpr int BM = 128;
    constexpr int BK = 32;
    constexpr int STAGES = 3;
    constexpr int NT = (BN / 2) / 8;
    constexpr int ASZ = BM * BK;
    constexpr int LDB_S = BN + 8;
    constexpr int BSZ = TRANSB ? (BN * BK) : (BK * LDB_S);

    const int z = blockIdx.z;
    A += (long long)(z / div) * aOuter + (long long)(z % div) * aInner;
    B += (long long)(z / div) * bOuter + (long long)(z % div) * bInner;
    C += (long long)(z / div) * cOuter + (long long)(z % div) * cInner;

    extern __shared__ float sm[];
    float* Asm = sm;
    float* Bsm = sm + STAGES * ASZ;

    const int tid  = threadIdx.x;
    const int lane = tid & 31;
    const int warp = tid >> 5;
    const int warp_m = (warp >> 1) * 32;
    const int warp_n = (warp & 1) * (BN / 2);
    const int m0 = blockIdx.y * BM;
    const int n0 = blockIdx.x * BN;
    const int Kiters = K / BK;

    const uint32_t a_base = smem_u32(Asm);
    const uint32_t b_base = smem_u32(Bsm);

    auto issue_stage = [&](int it) {
        if (it < Kiters) {
            const int s  = it % STAGES;
            const int k0 = it * BK;
#pragma unroll
            for (int i = 0; i < 4; i++) {
                const int idx = tid + i * 256;
                const int r = idx >> 3;
                const int g = idx & 7;
                const float* src = A + (size_t)(m0 + r) * lda + k0 + g * 4;
                cp_async16(a_base + (uint32_t)(s * ASZ + (r * 8 + (g ^ (r & 7))) * 4) * 4, src);
            }
            if (TRANSB) {
#pragma unroll
                for (int i = 0; i < BN / 32; i++) {
                    const int idx = tid + i * 256;
                    const int r = idx >> 3;
                    const int g = idx & 7;
                    const float* src = B + (size_t)(n0 + r) * ldb + k0 + g * 4;
                    cp_async16(b_base + (uint32_t)(s * BSZ + (r * 8 + (g ^ (r & 7))) * 4) * 4, src);
                }
            } else {
#pragma unroll
                for (int i = 0; i < BN / 32; i++) {
                    const int idx = tid + i * 256;
                    const int r = idx / (BN / 4);
                    const int g = idx % (BN / 4);
                    const float* src = B + (size_t)(k0 + r) * ldb + n0 + g * 4;
                    cp_async16(b_base + (uint32_t)(s * BSZ + r * LDB_S + g * 4) * 4, src);
                }
            }
        }
        cp_commit();
    };

    float acc[2][NT][4];
#pragma unroll
    for (int mi = 0; mi < 2; mi++)
#pragma unroll
        for (int nj = 0; nj < NT; nj++)
#pragma unroll
            for (int c = 0; c < 4; c++) acc[mi][nj][c] = 0.f;

    issue_stage(0);
    issue_stage(1);

    const int e = lane & 3;
    const int qd = lane >> 2;

    for (int it = 0; it < Kiters; ++it) {
        cp_wait<1>();
        __syncthreads();
        issue_stage(it + 2);

        const float* as = Asm + (it % STAGES) * ASZ;
        const float* bs = Bsm + (it % STAGES) * BSZ;

#pragma unroll
        for (int ks = 0; ks < 4; ks++) {
            const int g0 = ks * 2, g1 = ks * 2 + 1;
            uint32_t af[2][4];
#pragma unroll
            for (int mi = 0; mi < 2; mi++) {
                const int r0 = warp_m + mi * 16 + qd;
                const int r1 = r0 + 8;
                const float v0 = as[r0 * 32 + ((g0 ^ (r0 & 7)) << 2) + e];
                const float v1 = as[r1 * 32 + ((g0 ^ (r1 & 7)) << 2) + e];
                const float v2 = as[r0 * 32 + ((g1 ^ (r0 & 7)) << 2) + e];
                const float v3 = as[r1 * 32 + ((g1 ^ (r1 & 7)) << 2) + e];
                if (CVTA) {
                    af[mi][0] = f2tf32(v0); af[mi][1] = f2tf32(v1);
                    af[mi][2] = f2tf32(v2); af[mi][3] = f2tf32(v3);
                } else {
                    af[mi][0] = __float_as_uint(v0); af[mi][1] = __float_as_uint(v1);
                    af[mi][2] = __float_as_uint(v2); af[mi][3] = __float_as_uint(v3);
                }
            }
            uint32_t bf[NT][2];
#pragma unroll
            for (int nj = 0; nj < NT; nj++) {
                if (TRANSB) {
                    const int r = warp_n + nj * 8 + qd;
                    bf[nj][0] = __float_as_uint(bs[r * 32 + ((g0 ^ (r & 7)) << 2) + e]);
                    bf[nj][1] = __float_as_uint(bs[r * 32 + ((g1 ^ (r & 7)) << 2) + e]);
                } else {
                    const int n = warp_n + nj * 8 + qd;
                    bf[nj][0] = __float_as_uint(bs[(ks * 8 + e) * LDB_S + n]);
                    bf[nj][1] = __float_as_uint(bs[(ks * 8 + e + 4) * LDB_S + n]);
                }
            }
#pragma unroll
            for (int mi = 0; mi < 2; mi++)
#pragma unroll
                for (int nj = 0; nj < NT; nj++)
                    mma_tf32(acc[mi][nj][0], acc[mi][nj][1], acc[mi][nj][2], acc[mi][nj][3],
                             af[mi][0], af[mi][1], af[mi][2], af[mi][3],
                             bf[nj][0], bf[nj][1]);
        }
        __syncthreads();
    }

    // ---- epilogue ----
#pragma unroll
    for (int mi = 0; mi < 2; mi++) {
#pragma unroll
        for (int nj = 0; nj < NT; nj++) {
            const int row0 = m0 + warp_m + mi * 16 + qd;
            const int col  = n0 + warp_n + nj * 8 + e * 2;
            float2 v0, v1;
            v0.x = acc[mi][nj][0] * alpha;
            v0.y = acc[mi][nj][1] * alpha;
            v1.x = acc[mi][nj][2] * alpha;
            v1.y = acc[mi][nj][3] * alpha;
            if (bias) {
                const float b0 = bias[col], b1 = bias[col + 1];
                v0.x += b0; v0.y += b1;
                v1.x += b0; v1.y += b1;
            }
            if (EPI == 1) {
                v0.x = tf32r(v0.x); v0.y = tf32r(v0.y);
                v1.x = tf32r(v1.x); v1.y = tf32r(v1.y);
            }
            *(float2*)&C[(size_t)row0 * ldc + col] = v0;
            *(float2*)&C[(size_t)(row0 + 8) * ldc + col] = v1;
        }
    }
}

// ---------------------------------------------------------------------------
// Head-mix + attn_prev + softmax. One CTA per (b, q). (R3 verbatim)
// ---------------------------------------------------------------------------
#define MIX_SMEM_BYTES ((16 * 1024 + 256 + 8) * 4)

__global__ __launch_bounds__(256)
void mix_softmax_kernel(const float* __restrict__ scores,
                        const float* __restrict__ attn_prev,
                        const float* __restrict__ W_th,
                        float* __restrict__ attn)
{
    extern __shared__ float sh[];
    float* s_sc  = sh;
    float* s_w   = sh + 16 * 1024;
    float* s_red = s_w + 256;

    const int tid = threadIdx.x;
    const int bq  = blockIdx.x;
    const int b   = bq >> 10;
    const int q   = bq & 1023;
    const int lane = tid & 31;
    const int warp = tid >> 5;

#pragma unroll
    for (int h = 0; h < 16; h++) {
        const float4* src =
            (const float4*)(scores + ((size_t)(b * 16 + h) * 1024 + q) * 1024);
        ((float4*)(s_sc + h * 1024))[tid] = src[tid];
    }
    if (tid < 256) s_w[tid] = W_th[tid];
    __syncthreads();

    for (int g = 0; g < 16; g++) {
        const size_t rowbase = ((size_t)(b * 16 + g) * 1024 + q) * 1024;
        const float* prev = attn_prev + rowbase;
        float* dst = attn + rowbase;

        float vals[4];
        float mx = -1e30f;
#pragma unroll
        for (int i = 0; i < 4; i++) {
            const int k = tid + i * 256;
            float acc = prev[k];
#pragma unroll
            for (int h = 0; h < 16; h++)
                acc = fmaf(s_w[g * 16 + h], s_sc[h * 1024 + k], acc);
            vals[i] = acc;
            mx = fmaxf(mx, acc);
        }
#pragma unroll
        for (int o = 16; o; o >>= 1)
            mx = fmaxf(mx, __shfl_xor_sync(0xffffffffu, mx, o));
        if (lane == 0) s_red[warp] = mx;
        __syncthreads();
        float m = s_red[0];
#pragma unroll
        for (int w = 1; w < 8; w++) m = fmaxf(m, s_red[w]);
        __syncthreads();

        float sum = 0.f;
#pragma unroll
        for (int i = 0; i < 4; i++) {
            vals[i] = __expf(vals[i] - m);
            sum += vals[i];
        }
#pragma unroll
        for (int o = 16; o; o >>= 1)
            sum += __shfl_xor_sync(0xffffffffu, sum, o);
        if (lane == 0) s_red[warp] = sum;
        __syncthreads();
        float tot = 0.f;
#pragma unroll
        for (int w = 0; w < 8; w++) tot += s_red[w];
        const float inv = 1.0f / tot;
#pragma unroll
        for (int i = 0; i < 4; i++) dst[tid + i * 256] = vals[i] * inv;
        __syncthreads();
    }
}

// ---------------------------------------------------------------------------
// out = LayerNorm(a + b) * gamma + beta, rows of 1024. (R3 verbatim)
// ---------------------------------------------------------------------------
__global__ __launch_bounds__(256)
void add_ln_kernel(const float* __restrict__ a, const float* __restrict__ b,
                   const float* __restrict__ gam, const float* __restrict__ bet,
                   float* __restrict__ out)
{
    __shared__ float s_red[8];
    __shared__ float s_red2[8];
    const int row = blockIdx.x;
    const int tid = threadIdx.x;
    const int lane = tid & 31, warp = tid >> 5;

    const float4 va = ((const float4*)(a + (size_t)row * 1024))[tid];
    const float4 vb = ((const float4*)(b + (size_t)row * 1024))[tid];
    float4 v;
    v.x = va.x + vb.x; v.y = va.y + vb.y; v.z = va.z + vb.z; v.w = va.w + vb.w;

    float s  = v.x + v.y + v.z + v.w;
    float s2 = v.x * v.x + v.y * v.y + v.z * v.z + v.w * v.w;
#pragma unroll
    for (int o = 16; o; o >>= 1) {
        s  += __shfl_xor_sync(0xffffffffu, s, o);
        s2 += __shfl_xor_sync(0xffffffffu, s2, o);
    }
    if (lane == 0) { s_red[warp] = s; s_red2[warp] = s2; }
    __syncthreads();
    float ts = 0.f, ts2 = 0.f;
#pragma unroll
    for (int w = 0; w < 8; w++) { ts += s_red[w]; ts2 += s_red2[w]; }

    const float mu  = ts * (1.0f / 1024.0f);
    const float var = ts2 * (1.0f / 1024.0f) - mu * mu;
    const float inv = rsqrtf(var + EPS);

    const float4 g4 = ((const float4*)gam)[tid];
    const float4 b4 = ((const float4*)bet)[tid];
    float4 o;
    o.x = (v.x - mu) * inv * g4.x + b4.x;
    o.y = (v.y - mu) * inv * g4.y + b4.y;
    o.z = (v.z - mu) * inv * g4.z + b4.z;
    o.w = (v.w - mu) * inv * g4.w + b4.w;
    ((float4*)(out + (size_t)row * 1024))[tid] = o;
}

// ---------------------------------------------------------------------------
// GLU: t[r, j] = h[r, j] * relu(h[r, 2048 + j]) (R3 verbatim)
// ---------------------------------------------------------------------------
__global__ __launch_bounds__(256)
void glu_kernel(const float* __restrict__ h, float* __restrict__ t)
{
    const int i = blockIdx.x * blockDim.x + threadIdx.x;
    const int r = i >> 9;
    const int j = i & 511;
    const float4* hr = (const float4*)(h + (size_t)r * 4096);
    const float4 a = hr[j];
    const float4 g = hr[512 + j];
    float4 o;
    o.x = a.x * fmaxf(g.x, 0.f);
    o.y = a.y * fmaxf(g.y, 0.f);
    o.z = a.z * fmaxf(g.z, 0.f);
    o.w = a.w * fmaxf(g.w, 0.f);
    ((float4*)t)[i] = o;
}

// ---------------------------------------------------------------------------
// Launcher
// ---------------------------------------------------------------------------
extern "C" void kernel_launch(void* const* d_in, const int* in_sizes, int n_in,
                              void* d_out, int out_size)
{
    const float* x         = (const float*)d_in[0];
    const float* attn_prev = (const float*)d_in[1];
    const float* Wq        = (const float*)d_in[2];
    const float* Wk        = (const float*)d_in[3];
    const float* Wv        = (const float*)d_in[4];
    const float* W_th      = (const float*)d_in[5];
    const float* Wpv       = (const float*)d_in[6];
    const float* W1        = (const float*)d_in[7];
    const float* b1        = (const float*)d_in[8];
    const float* W2        = (const float*)d_in[9];
    const float* b2        = (const float*)d_in[10];
    const float* ln1g      = (const float*)d_in[11];
    const float* ln1b      = (const float*)d_in[12];
    const float* ln2g      = (const float*)d_in[13];
    const float* ln2b      = (const float*)d_in[14];

    float* out  = (float*)d_out;
    float* attn = out + (size_t)BB * PP * DD;

    float* s = nullptr;
    cudaGetSymbolAddress((void**)&s, g_scratch);
    float* xr   = s + OFF_XR;
    float* wqr  = s + OFF_WQ;
    float* wkr  = s + OFF_WK;
    float* wvr  = s + OFF_WV;
    float* wpvr = s + OFF_WPV;
    float* w1r  = s + OFF_W1R;
    float* w2r  = s + OFF_W2R;
    float* qb   = s + OFF_QB;
    float* kb   = s + OFF_KB;
    float* vb   = s + OFF_VB;
    float* sc   = s + OFF_SC;
    float* ob   = s + OFF_O;
    float* xsa  = s + OFF_XSA;
    float* x1   = s + OFF_X1;
    float* hb   = s + OFF_H;
    float* tb   = s + OFF_T;
    float* yb   = s + OFF_Y;    // aliases xr (dead after QKV projections)

    const int SM_NT = 3 * (128 * 32 + 128 * 32) * 4;           // 98304
    const int SM_NN = 3 * (128 * 32 + 32 * (64 + 8)) * 4;      // 76800
    cudaFuncSetAttribute((const void*)tgemm_kernel<128, true, 0, false>,
                         cudaFuncAttributeMaxDynamicSharedMemorySize, SM_NT);
    cudaFuncSetAttribute((const void*)tgemm_kernel<128, true, 1, false>,
                         cudaFuncAttributeMaxDynamicSharedMemorySize, SM_NT);
    cudaFuncSetAttribute((const void*)tgemm_kernel<128, true, 0, true>,
                         cudaFuncAttributeMaxDynamicSharedMemorySize, SM_NT);
    cudaFuncSetAttribute((const void*)tgemm_kernel<64, false, 1, true>,
                         cudaFuncAttributeMaxDynamicSharedMemorySize, SM_NN);
    cudaFuncSetAttribute(mix_softmax_kernel,
                         cudaFuncAttributeMaxDynamicSharedMemorySize, MIX_SMEM_BYTES);

    const int M = BB * PP;          // 4096
    const long long zero = 0;

    // ---- prep: tf32-round x + all weights (bit-identical to cvt-at-load) ----
    round_copy_kernel<<<4096, 256>>>(x, xr);
    round_copy_kernel<<<1024, 256>>>(Wq, wqr);
    round_copy_kernel<<<1024, 256>>>(Wk, wkr);
    round_copy_kernel<<<1024, 256>>>(Wv, wvr);
    round_copy_kernel<<<1024, 256>>>(Wpv, wpvr);
    round_copy_kernel<<<4096, 256>>>(W1, w1r);
    round_copy_kernel<<<2048, 256>>>(W2, w2r);

    // 1-3: Q (alpha=0.125), K, V projections — outputs tf32-rounded (EPI=1)
    {
        dim3 grid(DD / 128, M / 128, 1);
        tgemm_kernel<128, true, 1, false><<<grid, 256, SM_NT>>>(xr, wqr, nullptr, qb,
            M, HH * DQK, DD, DD, DD, HH * DQK,
            1, zero, zero, zero, zero, zero, zero, 0.125f);
        tgemm_kernel<128, true, 1, false><<<grid, 256, SM_NT>>>(xr, wkr, nullptr, kb,
            M, HH * DQK, DD, DD, DD, HH * DQK,
            1, zero, zero, zero, zero, zero, zero, 1.0f);
        tgemm_kernel<128, true, 1, false><<<grid, 256, SM_NT>>>(xr, wvr, nullptr, vb,
            M, HH * DV, DD, DD, DD, HH * DV,
            1, zero, zero, zero, zero, zero, zero, 1.0f);
    }

    // 4: scores[b,h] = q_bh @ k_bh^T  (batched over 64), both pre-rounded
    {
        dim3 grid(PP / 128, PP / 128, BB * HH);
        tgemm_kernel<128, true, 0, false><<<grid, 256, SM_NT>>>(qb, kb, nullptr, sc,
            PP, PP, DQK, HH * DQK, HH * DQK, PP,
            HH,
            (long long)PP * 1024, (long long)DQK,
            (long long)PP * 1024, (long long)DQK,
            (long long)HH * PP * PP, (long long)PP * PP,
            1.0f);
    }

    // 5: head mix + attn_prev + softmax -> attn (fp32, into d_out)
    mix_softmax_kernel<<<BB * PP, 256, MIX_SMEM_BYTES>>>(sc, attn_prev, W_th, attn);

    // 6: o[b,h] = attn_bh @ v_bh  (NN, attn needs CVTA; output rounded)
    {
        dim3 grid(1, PP / 128, BB * HH);
        tgemm_kernel<64, false, 1, true><<<grid, 256, SM_NN>>>(attn, vb, nullptr, ob,
            PP, DV, PP, PP, HH * DV, HH * DV,
            HH,
            (long long)HH * PP * PP, (long long)PP * PP,
            (long long)PP * 1024, (long long)DV,
            (long long)PP * 1024, (long long)DV,
            1.0f);
    }

    // 7: x_sa = o @ Wpv^T  (both pre-rounded)
    {
        dim3 grid(DD / 128, M / 128, 1);
        tgemm_kernel<128, true, 0, false><<<grid, 256, SM_NT>>>(ob, wpvr, nullptr, xsa,
            M, DD, HH * DV, HH * DV, HH * DV, DD,
            1, zero, zero, zero, zero, zero, zero, 1.0f);
    }

    // 8: x1 = LN(x + x_sa)  (fp32 store)
    add_ln_kernel<<<M, 256>>>(x, xsa, ln1g, ln1b, x1);

    // 9: h = x1 @ W1^T + b1   (x1 needs CVTA)
    {
        dim3 grid(DMID / 128, M / 128, 1);
        tgemm_kernel<128, true, 0, true><<<grid, 256, SM_NT>>>(x1, w1r, b1, hb,
            M, DMID, DD, DD, DD, DMID,
            1, zero, zero, zero, zero, zero, zero, 1.0f);
    }

    // 10: GLU -> t  (fp32)
    glu_kernel<<<(M * (DMID / 2) / 4) / 256, 256>>>(hb, tb);

    // 11: y = t @ W2^T + b2   (t needs CVTA)
    {
        dim3 grid(DD / 128, M / 128, 1);
        tgemm_kernel<128, true, 0, true><<<grid, 256, SM_NT>>>(tb, w2r, b2, yb,
            M, DD, DMID / 2, DMID / 2, DMID / 2, DD,
            1, zero, zero, zero, zero, zero, zero, 1.0f);
    }

    // 12: out = LN(x1 + y)
    add_ln_kernel<<<M, 256>>>(x1, yb, ln2g, ln2b, out);
}